// round 14
// baseline (speedup 1.0000x reference)
#include <cuda_runtime.h>
#include <cstdint>

#define BB 32
#define SS 8192
#define DD 64
#define FF 128
#define CS 64
#define NCH (SS / CS)   // 128 chunks

// Cross-CTA scan state. Aggregates are per (chunk, half): index p = ch*2+half.
__device__ float    g_aggA[2 * NCH * BB * FF];
__device__ float    g_aggC[2 * NCH * BB * FF];
__device__ int      g_flag[NCH * BB];
__device__ uint32_t g_wfragB[8192];   // [plane][kstep][ntile][lane][reg] bf16x2

// pack (lo, hi) fp32 -> bf16x2 (lo in lower 16 bits)
__device__ __forceinline__ uint32_t bf16x2(float lo, float hi) {
    uint32_t r;
    asm("cvt.rn.bf16x2.f32 %0, %1, %2;" : "=r"(r) : "f"(hi), "f"(lo));
    return r;
}
// split: returns big bf16x2, writes residual bf16x2
__device__ __forceinline__ uint32_t split_pack(float e0, float e1, uint32_t& sres) {
    const uint32_t b = bf16x2(e0, e1);
    const float f0 = __uint_as_float(b << 16);
    const float f1 = __uint_as_float(b & 0xFFFF0000u);
    sres = bf16x2(e0 - f0, e1 - f1);
    return b;
}

// ---------------------------------------------------------------------------
// Combined setup: zero flags + W -> bf16 (big, small) B-fragments.
// ---------------------------------------------------------------------------
__global__ void setup_kernel(const float* __restrict__ w)
{
    const int i = blockIdx.x * 256 + threadIdx.x;
    if (i < NCH * BB) g_flag[i] = 0;
    const int o = i - NCH * BB;
    if (o >= 0 && o < 8192) {
        const int reg = o & 1, lane = (o >> 1) & 31, nt = (o >> 6) & 15;
        const int ks = (o >> 10) & 3, plane = (o >> 12) & 1;
        const int group = lane >> 2, tig = lane & 3;
        const int k0  = ks * 16 + tig * 2 + reg * 8;
        const int col = nt * 8 + group;
        const float v0 = w[k0 * FF + col];
        const float v1 = w[(k0 + 1) * FF + col];
        uint32_t s;
        const uint32_t b = split_pack(v0, v1, s);
        g_wfragB[o] = plane ? s : b;
    }
}

// SMEM word offsets (total 28672 words = 112 KB -> 2 CTAs/SM)
#define SM_WF 0        // B frags: 8192 u32 (32 KB)
#define SM_E  8192     // A staging: EB 2048 + ES 2048 u32 (16 KB, swizzled)
#define SMA   12288    // k_s -> ratio: 64 x 128, XOR-swizzled cols
#define SMV   20480    // v_f / c: 64 x 128, XOR-swizzled cols
#define SM_FLOATS 28672
#define E_BYTE (SM_E * 4)   // 32768

#define GATE(x) (((x) > 0.5f) ? (x) : 0.f)

#define LDM4(r, a)                                                            \
    asm volatile("ldmatrix.sync.aligned.m8n8.x4.shared.b16 {%0,%1,%2,%3}, [%4];" \
        : "=r"((r)[0]), "=r"((r)[1]), "=r"((r)[2]), "=r"((r)[3]) : "r"(a))

#define MMAB(c, a, bb)                                                        \
    asm volatile("mma.sync.aligned.m16n8k16.row.col.f32.bf16.bf16.f32 "       \
        "{%0,%1,%2,%3}, {%4,%5,%6,%7}, {%8,%9}, {%0,%1,%2,%3};"               \
        : "+f"((c)[0]), "+f"((c)[1]), "+f"((c)[2]), "+f"((c)[3])              \
        : "r"((a)[0]), "r"((a)[1]), "r"((a)[2]), "r"((a)[3]),                 \
          "r"((bb).x), "r"((bb).y))

// Load whole 64x64 input tile: thread = (row tid>>2, k-quarter tid&3)
#define LOADX(xptr)                                                           \
    do {                                                                      \
        const float4* _p4 = (const float4*)(xptr);                            \
        _Pragma("unroll")                                                     \
        for (int _j = 0; _j < 4; _j++) xr[_j] = _p4[xbase + _j];              \
    } while (0)

// exp + bf16-split + swizzled store of both planes (conflict-free STS.128)
#define CONV_INPUT()                                                          \
    do {                                                                      \
        const int _r = tid >> 2, _kq = tid & 3;                               \
        float _e[16];                                                         \
        _Pragma("unroll")                                                     \
        for (int _j = 0; _j < 4; _j++) {                                      \
            _e[4*_j+0] = __expf(xr[_j].x); _e[4*_j+1] = __expf(xr[_j].y);     \
            _e[4*_j+2] = __expf(xr[_j].z); _e[4*_j+3] = __expf(xr[_j].w);     \
        }                                                                     \
        _Pragma("unroll")                                                     \
        for (int _cc = 0; _cc < 2; _cc++) {                                   \
            uint4 _ub, _us;                                                   \
            _ub.x = split_pack(_e[_cc*8+0], _e[_cc*8+1], _us.x);              \
            _ub.y = split_pack(_e[_cc*8+2], _e[_cc*8+3], _us.y);              \
            _ub.z = split_pack(_e[_cc*8+4], _e[_cc*8+5], _us.z);              \
            _ub.w = split_pack(_e[_cc*8+6], _e[_cc*8+7], _us.w);              \
            const int _sw = (_kq * 2 + _cc) ^ (_r & 7);                       \
            *(uint4*)(smc + E_BYTE + _r * 128 + _sw * 16)        = _ub;       \
            *(uint4*)(smc + E_BYTE + 8192 + _r * 128 + _sw * 16) = _us;       \
        }                                                                     \
    } while (0)

// 3-term bf16 mma over K=64: acc[mt][nt][4]
#define MMA_GEMM()                                                            \
    do {                                                                      \
        _Pragma("unroll")                                                     \
        for (int _ks = 0; _ks < 4; _ks++) {                                   \
            const uint32_t _swz = (uint32_t)((((_ks*2 + lhi) ^ (lane & 7))) << 4); \
            uint32_t _ab[2][4], _as[2][4];                                    \
            _Pragma("unroll")                                                 \
            for (int _mt = 0; _mt < 2; _mt++) {                               \
                const uint32_t _adr = eb_u32 + (uint32_t)((lrow0 + _mt*16) * 128) + _swz; \
                LDM4(_ab[_mt], _adr);                                         \
                LDM4(_as[_mt], _adr + 8192);                                  \
            }                                                                 \
            _Pragma("unroll")                                                 \
            for (int _nt = 0; _nt < 4; _nt++) {                               \
                const uint2 _Bb = *(const uint2*)&smu[(_ks*16 + wn*4 + _nt)*64 + lane*2];       \
                const uint2 _Bs = *(const uint2*)&smu[((4+_ks)*16 + wn*4 + _nt)*64 + lane*2];   \
                _Pragma("unroll")                                             \
                for (int _mt = 0; _mt < 2; _mt++) {                           \
                    MMAB(acc[_mt][_nt], _ab[_mt], _Bb);                       \
                    MMAB(acc[_mt][_nt], _ab[_mt], _Bs);                       \
                    MMAB(acc[_mt][_nt], _as[_mt], _Bb);                       \
                }                                                             \
            }                                                                 \
        }                                                                     \
    } while (0)

#define ZEROACC()                                                             \
    do {                                                                      \
        _Pragma("unroll") for (int _m = 0; _m < 2; _m++)                      \
        _Pragma("unroll") for (int _n = 0; _n < 4; _n++)                      \
        _Pragma("unroll") for (int _i = 0; _i < 4; _i++) acc[_m][_n][_i] = 0.f; \
    } while (0)

// ---------------------------------------------------------------------------
// Fused: bf16 3-term mma.sync feature GEMMs + gates + chunked scan (per-half
// shfl aggregates, decoupled lookback, ratio fused into cumsum) + output.
// CTA = 64 s-rows x 128 F, 256 thr / 8 warps, 2 CTAs/SM.
// ---------------------------------------------------------------------------
__global__ __launch_bounds__(256, 2)
void fused_sla(const float* __restrict__ q, const float* __restrict__ k,
               const float* __restrict__ v, float* __restrict__ out)
{
    extern __shared__ float sm[];
    uint32_t* smu = (uint32_t*)sm;
    char* smc = (char*)sm;
    const int tid = threadIdx.x, lane = tid & 31, w8 = tid >> 5;
    const int wn = w8 & 3, wm = w8 >> 2;
    const int group = lane >> 2, tig = lane & 3;
    const int lhi = (lane >> 4) & 1;
    const int lrow0 = wm * 32 + (lane & 7) + ((lane >> 3) & 1) * 8;
    const int b = blockIdx.x, ch = blockIdx.y;
    const int xbase = (tid >> 2) * 16 + (tid & 3) * 4;
    const size_t ibase = ((size_t)b * SS + ch * CS) * DD;
    const uint32_t eb_u32 = (uint32_t)__cvta_generic_to_shared(smc + E_BYTE);

    float4 xr[4];
    float acc[2][4][4];

    LOADX(v + ibase);
    // B fragments -> smem (coalesced)
#pragma unroll
    for (int t = 0; t < 8; t++)
        ((uint4*)smu)[tid + t * 256] = ((const uint4*)g_wfragB)[tid + t * 256];
    CONV_INPUT();                      // V -> E
    LOADX(k + ibase);
    __syncthreads();

    // ===== V GEMM -> v_f to SMV =====
    ZEROACC();
    MMA_GEMM();
#pragma unroll
    for (int mt = 0; mt < 2; mt++)
#pragma unroll
        for (int nt = 0; nt < 4; nt++) {
            const int col = wn * 32 + nt * 8 + tig * 2;
            const int cs  = col ^ (group << 2);        // rA&7 == group
            const int rA = wm * 32 + mt * 16 + group;
            *(float2*)&sm[SMV + rA * 128 + cs]       = make_float2(acc[mt][nt][0], acc[mt][nt][1]);
            *(float2*)&sm[SMV + (rA + 8) * 128 + cs] = make_float2(acc[mt][nt][2], acc[mt][nt][3]);
        }
    __syncthreads();                   // E free

    CONV_INPUT();                      // K -> E
    LOADX(q + ibase);
    __syncthreads();

    // ===== K GEMM -> gate -> a (SMA), c = a*v_f (SMV), shfl half-aggregates =====
    ZEROACC();
    MMA_GEMM();
#pragma unroll
    for (int nt = 0; nt < 4; nt++) {
        const int col = wn * 32 + nt * 8 + tig * 2;
        const int cs  = col ^ (group << 2);
        float sAx = 0.f, sAy = 0.f, sCx = 0.f, sCy = 0.f;
#pragma unroll
        for (int mt = 0; mt < 2; mt++) {
            const int rA = wm * 32 + mt * 16 + group;
            const float2 vf0 = *(const float2*)&sm[SMV + rA * 128 + cs];
            const float2 vf1 = *(const float2*)&sm[SMV + (rA + 8) * 128 + cs];
            const float a0 = GATE(acc[mt][nt][0]), a1 = GATE(acc[mt][nt][1]);
            const float a2 = GATE(acc[mt][nt][2]), a3 = GATE(acc[mt][nt][3]);
            const float c0 = a0 * vf0.x, c1 = a1 * vf0.y;
            const float c2 = a2 * vf1.x, c3 = a3 * vf1.y;
            *(float2*)&sm[SMA + rA * 128 + cs]       = make_float2(a0, a1);
            *(float2*)&sm[SMA + (rA + 8) * 128 + cs] = make_float2(a2, a3);
            *(float2*)&sm[SMV + rA * 128 + cs]       = make_float2(c0, c1);
            *(float2*)&sm[SMV + (rA + 8) * 128 + cs] = make_float2(c2, c3);
            sAx += a0 + a2;  sAy += a1 + a3;
            sCx += c0 + c2;  sCy += c1 + c3;
        }
        // reduce over the 8 row-groups (masks 4, 8, 16)
#pragma unroll
        for (int m = 4; m <= 16; m <<= 1) {
            sAx += __shfl_xor_sync(0xFFFFFFFFu, sAx, m);
            sAy += __shfl_xor_sync(0xFFFFFFFFu, sAy, m);
            sCx += __shfl_xor_sync(0xFFFFFFFFu, sCx, m);
            sCy += __shfl_xor_sync(0xFFFFFFFFu, sCy, m);
        }
        if (lane < 4) {   // lane == tig, group 0: publish this warp's half-slice
            const int pcol = wn * 32 + nt * 8 + lane * 2;
            const size_t gi = (((size_t)(ch * 2 + wm)) * BB + b) * FF + pcol;
            *(float2*)&g_aggA[gi] = make_float2(sAx, sAy);
            *(float2*)&g_aggC[gi] = make_float2(sCx, sCy);
        }
    }
    if (lane < 4) __threadfence();
    __syncthreads();
    if (tid == 0) atomicExch(&g_flag[ch * BB + b], 1);

    CONV_INPUT();                      // Q -> E
    __syncthreads();

    // ===== Q GEMM -> gated q_s in acc =====
    ZEROACC();
    MMA_GEMM();
#pragma unroll
    for (int mt = 0; mt < 2; mt++)
#pragma unroll
        for (int nt = 0; nt < 4; nt++)
#pragma unroll
            for (int i = 0; i < 4; i++)
                acc[mt][nt][i] = GATE(acc[mt][nt][i]);

    // ===== lookback wait (parallel) =====
    if (tid < ch)
        while (((volatile int*)g_flag)[tid * BB + b] == 0) __nanosleep(64);
    __syncthreads();

    // ===== prefix (registers) + fused cumsum/ratio =====
    // thread = (half = tid>>7, col = tid&127); upper half includes own low half.
    {
        const int half = tid >> 7;
        const int colp = tid & 127;
        const int pend = 2 * ch + half;
        float pA0 = 0.f, pA1 = 0.f, pC0 = 0.f, pC1 = 0.f;
        int p = 0;
        for (; p + 1 < pend; p += 2) {
            pA0 += g_aggA[((size_t)p * BB + b) * FF + colp];
            pA1 += g_aggA[((size_t)(p + 1) * BB + b) * FF + colp];
            pC0 += g_aggC[((size_t)p * BB + b) * FF + colp];
            pC1 += g_aggC[((size_t)(p + 1) * BB + b) * FF + colp];
        }
        if (p < pend) {
            pA0 += g_aggA[((size_t)p * BB + b) * FF + colp];
            pC0 += g_aggC[((size_t)p * BB + b) * FF + colp];
        }
        float cA = pA0 + pA1, cC = pC0 + pC1;
        const int r0 = half * 32;
#pragma unroll
        for (int so = 0; so < 32; so += 8)
#pragma unroll
            for (int si = 0; si < 8; si++) {
                const int idx = (r0 + so + si) * 128 + (colp ^ (si << 2));
                cA += sm[SMA + idx];
                cC += sm[SMV + idx];
                sm[SMA + idx] = __fdividef(cC + 1e-8f, cA + 1e-8f);
            }
    }
    __syncthreads();

    // ===== output: out = q_s * ratio =====
    const size_t ob = ((size_t)b * SS + ch * CS) * FF;
#pragma unroll
    for (int mt = 0; mt < 2; mt++)
#pragma unroll
        for (int nt = 0; nt < 4; nt++) {
            const int col = wn * 32 + nt * 8 + tig * 2;
            const int cs  = col ^ (group << 2);
            const int rA = wm * 32 + mt * 16 + group;
            const float2 r0 = *(const float2*)&sm[SMA + rA * 128 + cs];
            const float2 r1 = *(const float2*)&sm[SMA + (rA + 8) * 128 + cs];
            float2 o0, o1;
            o0.x = acc[mt][nt][0] * r0.x;
            o0.y = acc[mt][nt][1] * r0.y;
            o1.x = acc[mt][nt][2] * r1.x;
            o1.y = acc[mt][nt][3] * r1.y;
            *(float2*)&out[ob + (size_t)rA * FF + col]       = o0;
            *(float2*)&out[ob + (size_t)(rA + 8) * FF + col] = o1;
        }
}

extern "C" void kernel_launch(void* const* d_in, const int* in_sizes, int n_in,
                              void* d_out, int out_size)
{
    const float* q = (const float*)d_in[0];
    const float* k = (const float*)d_in[1];
    const float* v = (const float*)d_in[2];
    const float* w = (const float*)d_in[3];
    float* out = (float*)d_out;

    setup_kernel<<<(NCH * BB + 8192 + 255) / 256, 256>>>(w);

    cudaFuncSetAttribute(fused_sla, cudaFuncAttributeMaxDynamicSharedMemorySize,
                         SM_FLOATS * 4);
    dim3 grid(BB, NCH);   // linear bid = ch*BB + b (chunk-major)
    fused_sla<<<grid, 256, SM_FLOATS * 4>>>(q, k, v, out);
}